// round 6
// baseline (speedup 1.0000x reference)
#include <cuda_runtime.h>

#define NN 100000
#define EE 3200000
#define GG 1024
#define SCAN_B 1024
#define NSCANB ((NN + SCAN_B - 1) / SCAN_B)   // 98

// ---- scratch (allocation-free: __device__ globals) ----
__device__ int   d_is64;
__device__ __align__(16) int   d_cnt_e[NN];        // in-degree (excl self loop)
__device__ __align__(16) int   d_off[NN + 1];      // CSR offsets
__device__ __align__(16) int   d_fill[NN];         // fill cursors
__device__ int   d_part[NSCANB];                   // scan partials
__device__ __align__(16) int2  d_rc[EE];           // interleaved (row,col)
__device__ __align__(16) int   d_adj[EE];          // CSR adjacency (rows, grouped by col)
__device__ float d_dinv[NN];
__device__ __align__(32) float d_p[NN * 8];        // layer-1 message: 5 floats in one 32B block
__device__ __align__(32) float d_s[NN * 8];        // layer-1 aggregate
__device__ __align__(32) float d_g2[NN * 8];       // layer-2 message: 8 floats = one 32B block
__device__ __align__(16) float d_sums[GG * 8];
__device__ float d_cnt[GG];

// init: zero counters/pools, detect index dtype (int64 high words are 0 for idx < 1e5)
__global__ void k_init(const int* __restrict__ ei32) {
    int i = blockIdx.x * blockDim.x + threadIdx.x;
    if (i < NN) { d_cnt_e[i] = 0; d_fill[i] = 0; }
    if (i < GG * 8) d_sums[i] = 0.0f;
    if (i < GG) d_cnt[i] = 0.0f;
    if (i == 0) {
        int all0 = 1;
        for (int k = 0; k < 64; k++)
            if (ei32[2 * k + 1] != 0) { all0 = 0; break; }
        d_is64 = all0;
    }
}

// count: convert edges to int2 + in-degree histogram
__global__ void __launch_bounds__(256) k_count(const void* __restrict__ ei, int E) {
    int e = blockIdx.x * blockDim.x + threadIdx.x;
    if (e >= E) return;
    int r, c;
    if (d_is64) {
        const long long* p = (const long long*)ei;
        r = (int)p[e]; c = (int)p[E + e];
    } else {
        const int* p = (const int*)ei;
        r = p[e]; c = p[E + e];
    }
    d_rc[e] = make_int2(r, c);
    atomicAdd(&d_cnt_e[c], 1);
}

// scan level 1: per-block exclusive scan of counts (Hillis-Steele in smem)
__global__ void k_scan1() {
    __shared__ int sm[SCAN_B];
    int i = blockIdx.x * SCAN_B + threadIdx.x;
    int v = (i < NN) ? d_cnt_e[i] : 0;
    sm[threadIdx.x] = v;
    __syncthreads();
#pragma unroll
    for (int s = 1; s < SCAN_B; s <<= 1) {
        int t = (threadIdx.x >= s) ? sm[threadIdx.x - s] : 0;
        __syncthreads();
        sm[threadIdx.x] += t;
        __syncthreads();
    }
    if (i < NN) d_off[i] = sm[threadIdx.x] - v;   // exclusive within block
    if (threadIdx.x == SCAN_B - 1) d_part[blockIdx.x] = sm[SCAN_B - 1];
}

// scan level 2: serial exclusive scan of 98 block partials
__global__ void k_scan2(int E) {
    if (threadIdx.x != 0 || blockIdx.x != 0) return;
    int run = 0;
    for (int b = 0; b < NSCANB; b++) {
        int t = d_part[b];
        d_part[b] = run;
        run += t;
    }
    d_off[NN] = run;   // == E
}

// scan level 3: add block base
__global__ void k_scan3() {
    int i = blockIdx.x * blockDim.x + threadIdx.x;
    if (i < NN) d_off[i] += d_part[i >> 10];
}

// fill CSR adjacency: adj slots grouped by col contain row indices
__global__ void __launch_bounds__(256) k_fill(int E) {
    int e = blockIdx.x * blockDim.x + threadIdx.x;
    if (e >= E) return;
    int2 rc = d_rc[e];
    int pos = d_off[rc.y] + atomicAdd(&d_fill[rc.y], 1);
    d_adj[pos] = rc.x;
}

// node prologue: dinv = rsqrt(1 + indeg); message p = (dinv*x0, dinv*xyz | dinv)
__global__ void k_node0(const float* __restrict__ x) {
    int i = blockIdx.x * blockDim.x + threadIdx.x;
    if (i >= NN) return;
    float dinv = rsqrtf(1.0f + (float)d_cnt_e[i]);
    d_dinv[i] = dinv;
    float4 xi = reinterpret_cast<const float4*>(x)[i];
    reinterpret_cast<float4*>(&d_p[i * 8])[0] =
        make_float4(dinv * xi.x, dinv * xi.y, dinv * xi.z, dinv * xi.w);
    d_p[i * 8 + 4] = dinv;
}

// layer-1 aggregation: warp per node, pull-based, no atomics.
// s[c] = p[c] + sum_{r in in(c)} p[r]
__global__ void __launch_bounds__(256) k_agg1() {
    int w = (blockIdx.x * blockDim.x + threadIdx.x) >> 5;
    int lane = threadIdx.x & 31;
    if (w >= NN) return;
    int beg = d_off[w], end = d_off[w + 1];
    float4 a4 = make_float4(0.f, 0.f, 0.f, 0.f);
    float  a1 = 0.f;
    if (lane == 0) {  // self loop
        a4 = reinterpret_cast<const float4*>(&d_p[w * 8])[0];
        a1 = d_p[w * 8 + 4];
    }
    for (int j = beg + lane; j < end; j += 32) {
        int r = d_adj[j];
        float4 v = reinterpret_cast<const float4*>(&d_p[r * 8])[0];
        a4.x += v.x; a4.y += v.y; a4.z += v.z; a4.w += v.w;
        a1 += d_p[r * 8 + 4];
    }
#pragma unroll
    for (int m = 16; m; m >>= 1) {
        a4.x += __shfl_xor_sync(0xffffffffu, a4.x, m);
        a4.y += __shfl_xor_sync(0xffffffffu, a4.y, m);
        a4.z += __shfl_xor_sync(0xffffffffu, a4.z, m);
        a4.w += __shfl_xor_sync(0xffffffffu, a4.w, m);
        a1   += __shfl_xor_sync(0xffffffffu, a1, m);
    }
    if (lane == 0) {
        reinterpret_cast<float4*>(&d_s[w * 8])[0] = a4;
        d_s[w * 8 + 4] = a1;
    }
}

// node mid: reconstruct 7-dim aggregate, W1+b1, tanh, g2 = (h1 @ W2^T) * dinv
__global__ void k_node1(const float* __restrict__ W_emb,
                        const float* __restrict__ b_emb,
                        const float* __restrict__ W1,
                        const float* __restrict__ b1,
                        const float* __restrict__ W2) {
    int i = blockIdx.x * blockDim.x + threadIdx.x;
    if (i >= NN) return;
    float dinv = d_dinv[i];
    float4 S4 = reinterpret_cast<const float4*>(&d_s[i * 8])[0];
    float  S1 = d_s[i * 8 + 4];
    float a[7];
#pragma unroll
    for (int j = 0; j < 4; j++)
        a[j] = dinv * fmaf(W_emb[j], S4.x, b_emb[j] * S1);
    a[4] = dinv * S4.y;
    a[5] = dinv * S4.z;
    a[6] = dinv * S4.w;
    float h[16];
#pragma unroll
    for (int k = 0; k < 16; k++) {
        float s = b1[k];
#pragma unroll
        for (int j = 0; j < 7; j++) s = fmaf(W1[k * 7 + j], a[j], s);
        h[k] = tanhf(s);
    }
#pragma unroll
    for (int m = 0; m < 8; m++) {
        float s = 0.0f;
#pragma unroll
        for (int k = 0; k < 16; k++) s = fmaf(W2[m * 16 + k], h[k], s);
        d_g2[i * 8 + m] = s * dinv;
    }
}

// layer-2 aggregation + tanh + batch pooling: warp per node, no acc round-trip.
__global__ void __launch_bounds__(256) k_agg2(const void* __restrict__ batch,
                                              const float* __restrict__ b2) {
    int w = (blockIdx.x * blockDim.x + threadIdx.x) >> 5;
    int lane = threadIdx.x & 31;
    if (w >= NN) return;
    int beg = d_off[w], end = d_off[w + 1];
    float v[8];
#pragma unroll
    for (int k = 0; k < 8; k++) v[k] = 0.f;
    if (lane == 0) {  // self loop
        float4 s0 = reinterpret_cast<const float4*>(&d_g2[w * 8])[0];
        float4 s1 = reinterpret_cast<const float4*>(&d_g2[w * 8])[1];
        v[0] = s0.x; v[1] = s0.y; v[2] = s0.z; v[3] = s0.w;
        v[4] = s1.x; v[5] = s1.y; v[6] = s1.z; v[7] = s1.w;
    }
    for (int j = beg + lane; j < end; j += 32) {
        int r = d_adj[j];
        float4 s0 = reinterpret_cast<const float4*>(&d_g2[r * 8])[0];
        float4 s1 = reinterpret_cast<const float4*>(&d_g2[r * 8])[1];
        v[0] += s0.x; v[1] += s0.y; v[2] += s0.z; v[3] += s0.w;
        v[4] += s1.x; v[5] += s1.y; v[6] += s1.z; v[7] += s1.w;
    }
#pragma unroll
    for (int k = 0; k < 8; k++)
#pragma unroll
        for (int m = 16; m; m >>= 1)
            v[k] += __shfl_xor_sync(0xffffffffu, v[k], m);
    // all lanes now hold the 8 sums; lanes 0..7 pool one component each
    float dinv = d_dinv[w];
    int b = d_is64 ? (int)((const long long*)batch)[w] : ((const int*)batch)[w];
    if (lane < 8) {
        float h = tanhf(fmaf(dinv, v[lane], b2[lane]));
        atomicAdd(&d_sums[b * 8 + lane], h);
    } else if (lane == 8) {
        atomicAdd(&d_cnt[b], 1.0f);
    }
}

// final: out[g] = (sums/max(cnt,1)) . W3 + b3
__global__ void k_final(const float* __restrict__ W3, const float* __restrict__ b3,
                        float* __restrict__ out) {
    int g = blockIdx.x * blockDim.x + threadIdx.x;
    if (g >= GG) return;
    float c = fmaxf(d_cnt[g], 1.0f);
    float s = 0.0f;
#pragma unroll
    for (int k = 0; k < 8; k++) s = fmaf(d_sums[g * 8 + k], W3[k], s);
    out[g] = s / c + b3[0];
}

extern "C" void kernel_launch(void* const* d_in, const int* in_sizes, int n_in,
                              void* d_out, int out_size) {
    const float* x     = (const float*)d_in[0];
    const void*  ei    = d_in[1];
    const void*  batch = d_in[2];
    const float* W_emb = (const float*)d_in[3];
    const float* b_emb = (const float*)d_in[4];
    const float* W1    = (const float*)d_in[5];
    const float* b1    = (const float*)d_in[6];
    const float* W2    = (const float*)d_in[7];
    const float* b2    = (const float*)d_in[8];
    const float* W3    = (const float*)d_in[9];
    const float* b3    = (const float*)d_in[10];
    float* out = (float*)d_out;

    int E = in_sizes[1] / 2;
    if (E > EE) E = EE;

    int nb = (NN + 255) / 256;
    int eb = (E + 255) / 256;
    int wb = (NN * 32 + 255) / 256;   // warp-per-node grids

    k_init<<<nb, 256>>>((const int*)ei);
    k_count<<<eb, 256>>>(ei, E);
    k_scan1<<<NSCANB, SCAN_B>>>();
    k_scan2<<<1, 32>>>(E);
    k_scan3<<<nb, 256>>>();
    k_fill<<<eb, 256>>>(E);
    k_node0<<<nb, 256>>>(x);
    k_agg1<<<wb, 256>>>();
    k_node1<<<nb, 256>>>(W_emb, b_emb, W1, b1, W2);
    k_agg2<<<wb, 256>>>(batch, b2);
    k_final<<<(GG + 255) / 256, 256>>>(W3, b3, out);
}

// round 7
// speedup vs baseline: 1.4112x; 1.4112x over previous
#include <cuda_runtime.h>

#define NN 100000
#define EE 3200000
#define GG 1024

// ---- scratch (allocation-free: __device__ globals) ----
__device__ int   d_is64;                 // 1 if index inputs are int64
__device__ __align__(16) float d_deg[NN];
__device__ float d_dinv[NN];
__device__ __align__(16) int2  d_rc[EE];           // interleaved (row,col), int64 path only
__device__ __align__(32) float d_p[NN * 8];        // layer-1 message (5 floats in one 32B block)
__device__ __align__(32) float d_s[NN * 8];        // layer-1 aggregate
__device__ __align__(32) float d_g2[NN * 8];       // layer-2 message (8 floats = one 32B block)
__device__ __align__(32) float d_acc2[NN * 8];     // layer-2 aggregate
__device__ __align__(16) float d_sums[GG * 8];
__device__ float d_cnt[GG];

// init: deg=1 (self loop), pools=0, dtype detect (int64 idx < 1e5 -> high words all 0)
__global__ void k_init(const int* __restrict__ ei32) {
    int i = blockIdx.x * blockDim.x + threadIdx.x;
    if (i < NN) d_deg[i] = 1.0f;
    if (i < GG * 8) d_sums[i] = 0.0f;
    if (i < GG) d_cnt[i] = 0.0f;
    if (i == 0) {
        int all0 = 1;
        for (int k = 0; k < 64; k++)
            if (ei32[2 * k + 1] != 0) { all0 = 0; break; }
        d_is64 = all0;
    }
}

// prep: degree histogram; on int64 input also write compact int2 for the hot passes
__global__ void __launch_bounds__(256) k_prep(const void* __restrict__ ei, int E) {
    int e = blockIdx.x * blockDim.x + threadIdx.x;
    if (e >= E) return;
    if (d_is64) {
        const long long* p = (const long long*)ei;
        int r = (int)p[e];
        int c = (int)p[E + e];
        d_rc[e] = make_int2(r, c);
        atomicAdd(&d_deg[c], 1.0f);
    } else {
        const int* p = (const int*)ei;
        atomicAdd(&d_deg[p[E + e]], 1.0f);
    }
}

// node prologue: dinv; p = (dinv*x0, dinv*x, dinv*y, dinv*z | dinv); s init = p (self loop)
__global__ void k_node0(const float* __restrict__ x) {
    int i = blockIdx.x * blockDim.x + threadIdx.x;
    if (i >= NN) return;
    float dinv = rsqrtf(d_deg[i]);
    d_dinv[i] = dinv;
    float4 xi = reinterpret_cast<const float4*>(x)[i];
    float4 p4 = make_float4(dinv * xi.x, dinv * xi.y, dinv * xi.z, dinv * xi.w);
    reinterpret_cast<float4*>(&d_p[i * 8])[0] = p4;
    d_p[i * 8 + 4] = dinv;
    reinterpret_cast<float4*>(&d_s[i * 8])[0] = p4;
    d_s[i * 8 + 4] = dinv;
}

__device__ __forceinline__ void load_rc(const void* ei, int E, int e, int& r, int& c) {
    if (d_is64) {
        int2 rc = d_rc[e];
        r = rc.x; c = rc.y;
    } else {
        const int* p = (const int*)ei;
        r = __ldg(&p[e]);
        c = __ldg(&p[E + e]);
    }
}

// edge scatter layer 1: s[col] += p[row]  (red.v4 + red.f32), 2 edges per thread
__global__ void __launch_bounds__(256) k_edge1(const void* __restrict__ ei, int E) {
    int t = blockIdx.x * blockDim.x + threadIdx.x;
    int e0 = 2 * t, e1 = 2 * t + 1;
    if (e0 >= E) return;
    bool has1 = (e1 < E);
    int r0, c0, r1 = 0, c1 = 0;
    load_rc(ei, E, e0, r0, c0);
    if (has1) load_rc(ei, E, e1, r1, c1);
    const float* s0 = &d_p[r0 * 8];
    const float* s1 = &d_p[r1 * 8];
    float4 v0 = reinterpret_cast<const float4*>(s0)[0];
    float4 v1 = has1 ? reinterpret_cast<const float4*>(s1)[0] : make_float4(0, 0, 0, 0);
    float  w0 = s0[4];
    float  w1 = has1 ? s1[4] : 0.0f;
    float* dst0 = &d_s[c0 * 8];
    asm volatile("red.global.add.v4.f32 [%0], {%1,%2,%3,%4};"
                 :: "l"(dst0), "f"(v0.x), "f"(v0.y), "f"(v0.z), "f"(v0.w) : "memory");
    asm volatile("red.global.add.f32 [%0], %1;" :: "l"(dst0 + 4), "f"(w0) : "memory");
    if (has1) {
        float* dst1 = &d_s[c1 * 8];
        asm volatile("red.global.add.v4.f32 [%0], {%1,%2,%3,%4};"
                     :: "l"(dst1), "f"(v1.x), "f"(v1.y), "f"(v1.z), "f"(v1.w) : "memory");
        asm volatile("red.global.add.f32 [%0], %1;" :: "l"(dst1 + 4), "f"(w1) : "memory");
    }
}

// node mid: reconstruct 7-dim aggregate, W1+b1, tanh, g2 = (h1 @ W2^T) * dinv; acc2 = g2
__global__ void k_node1(const float* __restrict__ W_emb,
                        const float* __restrict__ b_emb,
                        const float* __restrict__ W1,
                        const float* __restrict__ b1,
                        const float* __restrict__ W2) {
    int i = blockIdx.x * blockDim.x + threadIdx.x;
    if (i >= NN) return;
    float dinv = d_dinv[i];
    float4 S4 = reinterpret_cast<const float4*>(&d_s[i * 8])[0];
    float  S1 = d_s[i * 8 + 4];
    float a[7];
#pragma unroll
    for (int j = 0; j < 4; j++)
        a[j] = dinv * fmaf(W_emb[j], S4.x, b_emb[j] * S1);
    a[4] = dinv * S4.y;
    a[5] = dinv * S4.z;
    a[6] = dinv * S4.w;
    float h[16];
#pragma unroll
    for (int k = 0; k < 16; k++) {
        float s = b1[k];
#pragma unroll
        for (int j = 0; j < 7; j++) s = fmaf(W1[k * 7 + j], a[j], s);
        h[k] = tanhf(s);
    }
#pragma unroll
    for (int m = 0; m < 8; m++) {
        float s = 0.0f;
#pragma unroll
        for (int k = 0; k < 16; k++) s = fmaf(W2[m * 16 + k], h[k], s);
        float g = s * dinv;
        d_g2[i * 8 + m] = g;
        d_acc2[i * 8 + m] = g;
    }
}

// edge scatter layer 2: acc2[col] += g2[row]  (2x red.v4), 2 edges per thread
__global__ void __launch_bounds__(256) k_edge2(const void* __restrict__ ei, int E) {
    int t = blockIdx.x * blockDim.x + threadIdx.x;
    int e0 = 2 * t, e1 = 2 * t + 1;
    if (e0 >= E) return;
    bool has1 = (e1 < E);
    int r0, c0, r1 = 0, c1 = 0;
    load_rc(ei, E, e0, r0, c0);
    if (has1) load_rc(ei, E, e1, r1, c1);
    const float4* s0 = reinterpret_cast<const float4*>(&d_g2[r0 * 8]);
    const float4* s1 = reinterpret_cast<const float4*>(&d_g2[r1 * 8]);
    float4 a0 = s0[0], b0 = s0[1];
    float4 a1 = has1 ? s1[0] : make_float4(0, 0, 0, 0);
    float4 b1v = has1 ? s1[1] : make_float4(0, 0, 0, 0);
    float4* dst0 = reinterpret_cast<float4*>(&d_acc2[c0 * 8]);
    asm volatile("red.global.add.v4.f32 [%0], {%1,%2,%3,%4};"
                 :: "l"(dst0), "f"(a0.x), "f"(a0.y), "f"(a0.z), "f"(a0.w) : "memory");
    asm volatile("red.global.add.v4.f32 [%0], {%1,%2,%3,%4};"
                 :: "l"(dst0 + 1), "f"(b0.x), "f"(b0.y), "f"(b0.z), "f"(b0.w) : "memory");
    if (has1) {
        float4* dst1 = reinterpret_cast<float4*>(&d_acc2[c1 * 8]);
        asm volatile("red.global.add.v4.f32 [%0], {%1,%2,%3,%4};"
                     :: "l"(dst1), "f"(a1.x), "f"(a1.y), "f"(a1.z), "f"(a1.w) : "memory");
        asm volatile("red.global.add.v4.f32 [%0], {%1,%2,%3,%4};"
                     :: "l"(dst1 + 1), "f"(b1v.x), "f"(b1v.y), "f"(b1v.z), "f"(b1v.w) : "memory");
    }
}

// node epilogue: h2 = tanh(dinv*acc2 + b2); pool into d_sums/d_cnt by batch
__global__ void k_node2(const void* __restrict__ batch, const float* __restrict__ b2) {
    int i = blockIdx.x * blockDim.x + threadIdx.x;
    if (i >= NN) return;
    float dinv = d_dinv[i];
    int b = d_is64 ? (int)((const long long*)batch)[i] : ((const int*)batch)[i];
#pragma unroll
    for (int k = 0; k < 8; k++) {
        float h = tanhf(fmaf(dinv, d_acc2[i * 8 + k], b2[k]));
        atomicAdd(&d_sums[b * 8 + k], h);
    }
    atomicAdd(&d_cnt[b], 1.0f);
}

// final: out[g] = (sums/max(cnt,1)) . W3 + b3
__global__ void k_final(const float* __restrict__ W3, const float* __restrict__ b3,
                        float* __restrict__ out) {
    int g = blockIdx.x * blockDim.x + threadIdx.x;
    if (g >= GG) return;
    float c = fmaxf(d_cnt[g], 1.0f);
    float s = 0.0f;
#pragma unroll
    for (int k = 0; k < 8; k++) s = fmaf(d_sums[g * 8 + k], W3[k], s);
    out[g] = s / c + b3[0];
}

extern "C" void kernel_launch(void* const* d_in, const int* in_sizes, int n_in,
                              void* d_out, int out_size) {
    const float* x     = (const float*)d_in[0];
    const void*  ei    = d_in[1];
    const void*  batch = d_in[2];
    const float* W_emb = (const float*)d_in[3];
    const float* b_emb = (const float*)d_in[4];
    const float* W1    = (const float*)d_in[5];
    const float* b1    = (const float*)d_in[6];
    const float* W2    = (const float*)d_in[7];
    const float* b2    = (const float*)d_in[8];
    const float* W3    = (const float*)d_in[9];
    const float* b3    = (const float*)d_in[10];
    float* out = (float*)d_out;

    int E = in_sizes[1] / 2;
    if (E > EE) E = EE;

    int nb = (NN + 255) / 256;
    int eb = (E + 255) / 256;
    int eb2 = (E / 2 + 255) / 256;   // 2 edges per thread

    k_init<<<nb, 256>>>((const int*)ei);
    k_prep<<<eb, 256>>>(ei, E);
    k_node0<<<nb, 256>>>(x);
    k_edge1<<<eb2, 256>>>(ei, E);
    k_node1<<<nb, 256>>>(W_emb, b_emb, W1, b1, W2);
    k_edge2<<<eb2, 256>>>(ei, E);
    k_node2<<<nb, 256>>>(batch, b2);
    k_final<<<(GG + 255) / 256, 256>>>(W3, b3, out);
}

// round 8
// speedup vs baseline: 2.0362x; 1.4429x over previous
#include <cuda_runtime.h>
#include <cuda_fp16.h>

#define NN 100000
#define EE 3200000
#define GG 1024

// ---- scratch (allocation-free: __device__ globals) ----
__device__ int   d_is64;                 // 1 if index inputs are int64
__device__ __align__(16) float  d_deg[NN];
__device__ float d_dinv[NN];
__device__ __align__(16) int2   d_rc[EE];          // interleaved (row,col), int64 path only
__device__ __align__(16) __half d_p[NN * 8];       // layer-1 message: 5 halves in 16B
__device__ __align__(16) __half d_s[NN * 8];       // layer-1 aggregate (fp16 atomics)
__device__ __align__(16) __half d_g2[NN * 8];      // layer-2 message: 8 halves in 16B
__device__ __align__(16) __half d_acc2[NN * 8];    // layer-2 aggregate (fp16 atomics)
__device__ __align__(16) float  d_sums[GG * 8];
__device__ float d_cnt[GG];

__device__ __forceinline__ unsigned h2u(__half2 h) { return *reinterpret_cast<unsigned*>(&h); }
__device__ __forceinline__ __half2 u2h(unsigned u) { return *reinterpret_cast<__half2*>(&u); }

// init: deg=1 (self loop), pools=0, dtype detect (int64 idx < 1e5 -> high words all 0)
__global__ void k_init(const int* __restrict__ ei32) {
    int i = blockIdx.x * blockDim.x + threadIdx.x;
    if (i < NN) d_deg[i] = 1.0f;
    if (i < GG * 8) d_sums[i] = 0.0f;
    if (i < GG) d_cnt[i] = 0.0f;
    if (i == 0) {
        int all0 = 1;
        for (int k = 0; k < 64; k++)
            if (ei32[2 * k + 1] != 0) { all0 = 0; break; }
        d_is64 = all0;
    }
}

// prep: degree histogram; on int64 input also write compact int2 for the hot passes
__global__ void __launch_bounds__(256) k_prep(const void* __restrict__ ei, int E) {
    int e = blockIdx.x * blockDim.x + threadIdx.x;
    if (e >= E) return;
    if (d_is64) {
        const long long* p = (const long long*)ei;
        int r = (int)p[e];
        int c = (int)p[E + e];
        d_rc[e] = make_int2(r, c);
        atomicAdd(&d_deg[c], 1.0f);
    } else {
        const int* p = (const int*)ei;
        atomicAdd(&d_deg[p[E + e]], 1.0f);
    }
}

// node prologue: dinv; p = pack16(dinv*x0, dinv*x, dinv*y, dinv*z, dinv, 0,0,0); s = p
__global__ void k_node0(const float* __restrict__ x) {
    int i = blockIdx.x * blockDim.x + threadIdx.x;
    if (i >= NN) return;
    float dinv = rsqrtf(d_deg[i]);
    d_dinv[i] = dinv;
    float4 xi = reinterpret_cast<const float4*>(x)[i];
    uint4 pk;
    pk.x = h2u(__floats2half2_rn(dinv * xi.x, dinv * xi.y));
    pk.y = h2u(__floats2half2_rn(dinv * xi.z, dinv * xi.w));
    pk.z = h2u(__floats2half2_rn(dinv, 0.0f));
    pk.w = 0u;
    reinterpret_cast<uint4*>(&d_p[i * 8])[0] = pk;
    reinterpret_cast<uint4*>(&d_s[i * 8])[0] = pk;
}

__device__ __forceinline__ void load_rc(const void* ei, int E, int e, int& r, int& c) {
    if (d_is64) {
        int2 rc = d_rc[e];
        r = rc.x; c = rc.y;
    } else {
        const int* p = (const int*)ei;
        r = __ldg(&p[e]);
        c = __ldg(&p[E + e]);
    }
}

// edge scatter layer 1: s[col] += p[row]   (one 16B gather + one red.v4.f16x2)
__global__ void __launch_bounds__(256) k_edge1(const void* __restrict__ ei, int E) {
    int e = blockIdx.x * blockDim.x + threadIdx.x;
    if (e >= E) return;
    int r, c;
    load_rc(ei, E, e, r, c);
    uint4 v = reinterpret_cast<const uint4*>(&d_p[r * 8])[0];
    asm volatile("red.global.add.noftz.v4.f16x2 [%0], {%1,%2,%3,%4};"
                 :: "l"(&d_s[c * 8]), "r"(v.x), "r"(v.y), "r"(v.z), "r"(v.w)
                 : "memory");
}

// node mid: unpack fp16 aggregate, reconstruct 7-dim, W1+b1, tanh, g2=(h1@W2^T)*dinv
__global__ void k_node1(const float* __restrict__ W_emb,
                        const float* __restrict__ b_emb,
                        const float* __restrict__ W1,
                        const float* __restrict__ b1,
                        const float* __restrict__ W2) {
    int i = blockIdx.x * blockDim.x + threadIdx.x;
    if (i >= NN) return;
    float dinv = d_dinv[i];
    uint4 sv = reinterpret_cast<const uint4*>(&d_s[i * 8])[0];
    float2 f0 = __half22float2(u2h(sv.x));   // S.x0, S.x
    float2 f1 = __half22float2(u2h(sv.y));   // S.y, S.z
    float2 f2 = __half22float2(u2h(sv.z));   // S1, -
    float a[7];
#pragma unroll
    for (int j = 0; j < 4; j++)
        a[j] = dinv * fmaf(W_emb[j], f0.x, b_emb[j] * f2.x);
    a[4] = dinv * f0.y;
    a[5] = dinv * f1.x;
    a[6] = dinv * f1.y;
    float h[16];
#pragma unroll
    for (int k = 0; k < 16; k++) {
        float s = b1[k];
#pragma unroll
        for (int j = 0; j < 7; j++) s = fmaf(W1[k * 7 + j], a[j], s);
        h[k] = tanhf(s);
    }
    float g[8];
#pragma unroll
    for (int m = 0; m < 8; m++) {
        float s = 0.0f;
#pragma unroll
        for (int k = 0; k < 16; k++) s = fmaf(W2[m * 16 + k], h[k], s);
        g[m] = s * dinv;
    }
    uint4 pk;
    pk.x = h2u(__floats2half2_rn(g[0], g[1]));
    pk.y = h2u(__floats2half2_rn(g[2], g[3]));
    pk.z = h2u(__floats2half2_rn(g[4], g[5]));
    pk.w = h2u(__floats2half2_rn(g[6], g[7]));
    reinterpret_cast<uint4*>(&d_g2[i * 8])[0] = pk;
    reinterpret_cast<uint4*>(&d_acc2[i * 8])[0] = pk;
}

// edge scatter layer 2: acc2[col] += g2[row]   (one 16B gather + one red.v4.f16x2)
__global__ void __launch_bounds__(256) k_edge2(const void* __restrict__ ei, int E) {
    int e = blockIdx.x * blockDim.x + threadIdx.x;
    if (e >= E) return;
    int r, c;
    load_rc(ei, E, e, r, c);
    uint4 v = reinterpret_cast<const uint4*>(&d_g2[r * 8])[0];
    asm volatile("red.global.add.noftz.v4.f16x2 [%0], {%1,%2,%3,%4};"
                 :: "l"(&d_acc2[c * 8]), "r"(v.x), "r"(v.y), "r"(v.z), "r"(v.w)
                 : "memory");
}

// node epilogue: h2 = tanh(dinv*acc2 + b2); pool into d_sums/d_cnt by batch
__global__ void k_node2(const void* __restrict__ batch, const float* __restrict__ b2) {
    int i = blockIdx.x * blockDim.x + threadIdx.x;
    if (i >= NN) return;
    float dinv = d_dinv[i];
    int b = d_is64 ? (int)((const long long*)batch)[i] : ((const int*)batch)[i];
    uint4 av = reinterpret_cast<const uint4*>(&d_acc2[i * 8])[0];
    float2 a0 = __half22float2(u2h(av.x));
    float2 a1 = __half22float2(u2h(av.y));
    float2 a2 = __half22float2(u2h(av.z));
    float2 a3 = __half22float2(u2h(av.w));
    float v[8] = {a0.x, a0.y, a1.x, a1.y, a2.x, a2.y, a3.x, a3.y};
#pragma unroll
    for (int k = 0; k < 8; k++) {
        float h = tanhf(fmaf(dinv, v[k], b2[k]));
        atomicAdd(&d_sums[b * 8 + k], h);
    }
    atomicAdd(&d_cnt[b], 1.0f);
}

// final: out[g] = (sums/max(cnt,1)) . W3 + b3
__global__ void k_final(const float* __restrict__ W3, const float* __restrict__ b3,
                        float* __restrict__ out) {
    int g = blockIdx.x * blockDim.x + threadIdx.x;
    if (g >= GG) return;
    float c = fmaxf(d_cnt[g], 1.0f);
    float s = 0.0f;
#pragma unroll
    for (int k = 0; k < 8; k++) s = fmaf(d_sums[g * 8 + k], W3[k], s);
    out[g] = s / c + b3[0];
}

extern "C" void kernel_launch(void* const* d_in, const int* in_sizes, int n_in,
                              void* d_out, int out_size) {
    const float* x     = (const float*)d_in[0];
    const void*  ei    = d_in[1];
    const void*  batch = d_in[2];
    const float* W_emb = (const float*)d_in[3];
    const float* b_emb = (const float*)d_in[4];
    const float* W1    = (const float*)d_in[5];
    const float* b1    = (const float*)d_in[6];
    const float* W2    = (const float*)d_in[7];
    const float* b2    = (const float*)d_in[8];
    const float* W3    = (const float*)d_in[9];
    const float* b3    = (const float*)d_in[10];
    float* out = (float*)d_out;

    int E = in_sizes[1] / 2;
    if (E > EE) E = EE;

    int nb = (NN + 255) / 256;
    int eb = (E + 255) / 256;

    k_init<<<nb, 256>>>((const int*)ei);
    k_prep<<<eb, 256>>>(ei, E);
    k_node0<<<nb, 256>>>(x);
    k_edge1<<<eb, 256>>>(ei, E);
    k_node1<<<nb, 256>>>(W_emb, b_emb, W1, b1, W2);
    k_edge2<<<eb, 256>>>(ei, E);
    k_node2<<<nb, 256>>>(batch, b2);
    k_final<<<(GG + 255) / 256, 256>>>(W3, b3, out);
}